// round 8
// baseline (speedup 1.0000x reference)
#include <cuda_runtime.h>
#include <cuda_bf16.h>
#include <math.h>
#include <stdint.h>

// Problem constants
#define BSZ 4
#define TSEQ 1024
#define CDIM 1024
#define NHEAD 16
#define HDIM 64
#define FFDIM 4096
#define MTOK (BSZ * TSEQ)   // 4096 tokens

// ---------------------------------------------------------------------------
// Scratch buffers (allocation-free: __device__ globals)
// ---------------------------------------------------------------------------
__device__ float g_q [MTOK * CDIM];
__device__ float g_k [MTOK * CDIM];
__device__ float g_v [MTOK * CDIM];
__device__ float g_x1[MTOK * CDIM];
__device__ __nv_bfloat16 g_lnb[MTOK * CDIM];    // LN output (bf16, GEMM A)
__device__ __nv_bfloat16 g_ab [MTOK * CDIM];    // attention output (bf16)
__device__ __nv_bfloat16 g_hb [MTOK * FFDIM];   // FFN hidden (bf16)
__device__ __nv_bfloat16 g_wq [CDIM * CDIM];
__device__ __nv_bfloat16 g_wk [CDIM * CDIM];
__device__ __nv_bfloat16 g_wv [CDIM * CDIM];
__device__ __nv_bfloat16 g_wp [CDIM * CDIM];
__device__ __nv_bfloat16 g_w1 [CDIM * FFDIM];
__device__ __nv_bfloat16 g_w2 [FFDIM * CDIM];

__device__ __forceinline__ uint32_t f2tf(float f) {
    uint32_t u;
    asm("cvt.rna.tf32.f32 %0, %1;" : "=r"(u) : "f"(f));
    return u;
}
// pack two floats to bf16x2: low half = lo, high half = hi
__device__ __forceinline__ uint32_t packbf(float lo, float hi) {
    uint32_t d;
    asm("cvt.rn.bf16x2.f32 %0, %1, %2;" : "=r"(d) : "f"(hi), "f"(lo));
    return d;
}

// ---------------------------------------------------------------------------
// fp32 -> bf16 conversion (weights), 8 elements/thread, exact grid
// ---------------------------------------------------------------------------
__global__ __launch_bounds__(256)
void f2b_kernel(const float* __restrict__ in, __nv_bfloat16* __restrict__ out)
{
    const size_t i = ((size_t)blockIdx.x * 256 + threadIdx.x) * 8;
    float4 v0 = *(const float4*)(in + i);
    float4 v1 = *(const float4*)(in + i + 4);
    uint4 o = make_uint4(packbf(v0.x, v0.y), packbf(v0.z, v0.w),
                         packbf(v1.x, v1.y), packbf(v1.z, v1.w));
    *(uint4*)(out + i) = o;
}

// ---------------------------------------------------------------------------
// LayerNorm: one block per row of 1024, 256 threads; bf16 output
// ---------------------------------------------------------------------------
__global__ __launch_bounds__(256)
void ln_kernel(const float* __restrict__ x, const float* __restrict__ gamma,
               const float* __restrict__ beta, __nv_bfloat16* __restrict__ out)
{
    const int row = blockIdx.x;
    const int tid = threadIdx.x;
    const float4* xr = (const float4*)(x + (size_t)row * CDIM);
    float4 v = xr[tid];
    float s  = v.x + v.y + v.z + v.w;
    float sq = v.x * v.x + v.y * v.y + v.z * v.z + v.w * v.w;
    #pragma unroll
    for (int o = 16; o > 0; o >>= 1) {
        s  += __shfl_xor_sync(0xffffffffu, s,  o);
        sq += __shfl_xor_sync(0xffffffffu, sq, o);
    }
    __shared__ float ss[8], ssq[8];
    const int w = tid >> 5, lane = tid & 31;
    if (lane == 0) { ss[w] = s; ssq[w] = sq; }
    __syncthreads();
    float ts = 0.f, tsq = 0.f;
    #pragma unroll
    for (int i = 0; i < 8; i++) { ts += ss[i]; tsq += ssq[i]; }
    const float mean = ts * (1.0f / CDIM);
    const float var  = tsq * (1.0f / CDIM) - mean * mean;
    const float inv  = rsqrtf(var + 1e-5f);

    float4 gv = ((const float4*)gamma)[tid];
    float4 bv = ((const float4*)beta)[tid];
    const float o0 = (v.x - mean) * inv * gv.x + bv.x;
    const float o1 = (v.y - mean) * inv * gv.y + bv.y;
    const float o2 = (v.z - mean) * inv * gv.z + bv.z;
    const float o3 = (v.w - mean) * inv * gv.w + bv.w;
    uint2 o2v = make_uint2(packbf(o0, o1), packbf(o2, o3));
    *(uint2*)(out + (size_t)row * CDIM + tid * 4) = o2v;
}

// ---------------------------------------------------------------------------
// BF16 tensor-core GEMM, all-bf16 inputs. 128x128x32 CTA tile, 256 threads
// = 8 warps (4M x 2N), warp tile 32x64 = 2x8 m16n8k16 atoms, 2 k16 substeps
// per stage. smem [kpair][m/n] stride 136 -> conflict-free fragment loads.
// No conversions in the mainloop (PRMT interleave for B k-pairs).
// EPI: 0 = bias, 1 = bias + residual, 2 = bias + exact GELU
// OUTBF: 1 -> bf16 output, 0 -> fp32 output
// ---------------------------------------------------------------------------
template <int EPI, int OUTBF>
__device__ __forceinline__
void gemm_bf_body(const __nv_bfloat16* __restrict__ A,
                  const __nv_bfloat16* __restrict__ W,
                  const float* __restrict__ bias, const float* __restrict__ res,
                  void* __restrict__ Cout, int Ndim, int Kdim, int m0, int n0)
{
    __shared__ uint32_t As[2][16][136];   // [kpair][m], bf16x2 (k even, k odd)
    __shared__ uint32_t Bs[2][16][136];   // [kpair][n]

    const int tid  = threadIdx.x;
    const int lane = tid & 31, warp = tid >> 5;
    const int wm = (warp & 3) * 32, wn = (warp >> 2) * 64;
    const int r = lane >> 2, c = lane & 3;

    // A: thread owns row ra, k-offsets kg and kg+16 (8 bf16 each)
    const int ra = tid & 127;
    const int kg = (tid >> 7) * 8;
    const int kp = kg >> 1;               // kpair base: 0 or 4
    // B: warp owns k-row-pairs (2w,2w+1) and (2w+16,2w+17), lane cols nb..nb+3
    const int nb = lane * 4;

    const __nv_bfloat16* Ap = A + (size_t)(m0 + ra) * Kdim + kg;
    const __nv_bfloat16* Bp = W + (size_t)(2 * warp) * Ndim + n0 + nb;

    float acc[2][8][4];
    #pragma unroll
    for (int mi = 0; mi < 2; mi++)
        #pragma unroll
        for (int ni = 0; ni < 8; ni++)
            #pragma unroll
            for (int q = 0; q < 4; q++) acc[mi][ni][q] = 0.f;

    uint4 a0 = *(const uint4*)Ap;
    uint4 a1 = *(const uint4*)(Ap + 16);
    uint2 b00 = *(const uint2*)Bp;
    uint2 b01 = *(const uint2*)(Bp + Ndim);
    uint2 b10 = *(const uint2*)(Bp + (size_t)16 * Ndim);
    uint2 b11 = *(const uint2*)(Bp + (size_t)17 * Ndim);

    // Stage buffer 0
    {
        As[0][kp + 0][ra] = a0.x; As[0][kp + 1][ra] = a0.y;
        As[0][kp + 2][ra] = a0.z; As[0][kp + 3][ra] = a0.w;
        As[0][kp + 8][ra] = a1.x; As[0][kp + 9][ra] = a1.y;
        As[0][kp +10][ra] = a1.z; As[0][kp +11][ra] = a1.w;
        uint4 t0 = make_uint4(__byte_perm(b00.x, b01.x, 0x5410),
                              __byte_perm(b00.x, b01.x, 0x7632),
                              __byte_perm(b00.y, b01.y, 0x5410),
                              __byte_perm(b00.y, b01.y, 0x7632));
        *(uint4*)&Bs[0][warp][nb] = t0;
        uint4 t1 = make_uint4(__byte_perm(b10.x, b11.x, 0x5410),
                              __byte_perm(b10.x, b11.x, 0x7632),
                              __byte_perm(b10.y, b11.y, 0x5410),
                              __byte_perm(b10.y, b11.y, 0x7632));
        *(uint4*)&Bs[0][warp + 8][nb] = t1;
    }
    __syncthreads();

    int buf = 0;
    for (int k0 = 32; k0 <= Kdim; k0 += 32) {
        if (k0 < Kdim) {
            a0  = *(const uint4*)(Ap + k0);
            a1  = *(const uint4*)(Ap + k0 + 16);
            b00 = *(const uint2*)(Bp + (size_t)k0 * Ndim);
            b01 = *(const uint2*)(Bp + (size_t)(k0 + 1) * Ndim);
            b10 = *(const uint2*)(Bp + (size_t)(k0 + 16) * Ndim);
            b11 = *(const uint2*)(Bp + (size_t)(k0 + 17) * Ndim);
        }

        #pragma unroll
        for (int s = 0; s < 2; s++) {
            const int kc = 8 * s + c;
            uint32_t af[2][4], bf[8][2];
            #pragma unroll
            for (int mi = 0; mi < 2; mi++) {
                af[mi][0] = As[buf][kc    ][wm + 16 * mi + r];
                af[mi][1] = As[buf][kc    ][wm + 16 * mi + r + 8];
                af[mi][2] = As[buf][kc + 4][wm + 16 * mi + r];
                af[mi][3] = As[buf][kc + 4][wm + 16 * mi + r + 8];
            }
            #pragma unroll
            for (int ni = 0; ni < 8; ni++) {
                bf[ni][0] = Bs[buf][kc    ][wn + 8 * ni + r];
                bf[ni][1] = Bs[buf][kc + 4][wn + 8 * ni + r];
            }
            #pragma unroll
            for (int mi = 0; mi < 2; mi++)
                #pragma unroll
                for (int ni = 0; ni < 8; ni++) {
                    asm volatile(
                        "mma.sync.aligned.m16n8k16.row.col.f32.bf16.bf16.f32 "
                        "{%0,%1,%2,%3}, {%4,%5,%6,%7}, {%8,%9}, {%0,%1,%2,%3};\n"
                        : "+f"(acc[mi][ni][0]), "+f"(acc[mi][ni][1]),
                          "+f"(acc[mi][ni][2]), "+f"(acc[mi][ni][3])
                        : "r"(af[mi][0]), "r"(af[mi][1]), "r"(af[mi][2]), "r"(af[mi][3]),
                          "r"(bf[ni][0]), "r"(bf[ni][1]));
                }
        }

        if (k0 < Kdim) {
            const int nbuf = buf ^ 1;
            As[nbuf][kp + 0][ra] = a0.x; As[nbuf][kp + 1][ra] = a0.y;
            As[nbuf][kp + 2][ra] = a0.z; As[nbuf][kp + 3][ra] = a0.w;
            As[nbuf][kp + 8][ra] = a1.x; As[nbuf][kp + 9][ra] = a1.y;
            As[nbuf][kp +10][ra] = a1.z; As[nbuf][kp +11][ra] = a1.w;
            uint4 t0 = make_uint4(__byte_perm(b00.x, b01.x, 0x5410),
                                  __byte_perm(b00.x, b01.x, 0x7632),
                                  __byte_perm(b00.y, b01.y, 0x5410),
                                  __byte_perm(b00.y, b01.y, 0x7632));
            *(uint4*)&Bs[nbuf][warp][nb] = t0;
            uint4 t1 = make_uint4(__byte_perm(b10.x, b11.x, 0x5410),
                                  __byte_perm(b10.x, b11.x, 0x7632),
                                  __byte_perm(b10.y, b11.y, 0x5410),
                                  __byte_perm(b10.y, b11.y, 0x7632));
            *(uint4*)&Bs[nbuf][warp + 8][nb] = t1;
            __syncthreads();
            buf = nbuf;
        }
    }

    #pragma unroll
    for (int mi = 0; mi < 2; mi++) {
        #pragma unroll
        for (int half = 0; half < 2; half++) {
            const int row = m0 + wm + 16 * mi + r + 8 * half;
            #pragma unroll
            for (int ni = 0; ni < 8; ni++) {
                const int col = n0 + wn + 8 * ni + 2 * c;
                float v0 = acc[mi][ni][2 * half + 0] + bias[col];
                float v1 = acc[mi][ni][2 * half + 1] + bias[col + 1];
                if (EPI == 1) {
                    v0 += res[(size_t)row * Ndim + col];
                    v1 += res[(size_t)row * Ndim + col + 1];
                }
                if (EPI == 2) {
                    v0 = 0.5f * v0 * (1.0f + erff(v0 * 0.7071067811865475f));
                    v1 = 0.5f * v1 * (1.0f + erff(v1 * 0.7071067811865475f));
                }
                if (OUTBF) {
                    ((uint32_t*)Cout)[((size_t)row * Ndim + col) >> 1] = packbf(v0, v1);
                } else {
                    *(float2*)&((float*)Cout)[(size_t)row * Ndim + col] = make_float2(v0, v1);
                }
            }
        }
    }
}

template <int EPI, int OUTBF>
__global__ __launch_bounds__(256)
void gemm_bf(const __nv_bfloat16* __restrict__ A, const __nv_bfloat16* __restrict__ W,
             const float* __restrict__ bias, const float* __restrict__ res,
             void* __restrict__ Cout, int Ndim, int Kdim)
{
    gemm_bf_body<EPI, OUTBF>(A, W, bias, res, Cout, Ndim, Kdim,
                             blockIdx.y * 128, blockIdx.x * 128);
}

// Fused QKV: blockIdx.z selects {W, bias, out}; fp32 outputs (attention reads fp32)
struct QKVParams {
    const __nv_bfloat16 *Wq, *Wk, *Wv;
    const float *bq, *bk, *bv;
    float *q, *k, *v;
};

__global__ __launch_bounds__(256)
void gemm_bf_qkv(const __nv_bfloat16* __restrict__ A, QKVParams p)
{
    const __nv_bfloat16* W; const float* b; float* o;
    if (blockIdx.z == 0)      { W = p.Wq; b = p.bq; o = p.q; }
    else if (blockIdx.z == 1) { W = p.Wk; b = p.bk; o = p.k; }
    else                      { W = p.Wv; b = p.bv; o = p.v; }
    gemm_bf_body<0, 0>(A, W, b, nullptr, o, CDIM, CDIM,
                       blockIdx.y * 128, blockIdx.x * 128);
}

// ---------------------------------------------------------------------------
// Causal flash attention with TF32 tensor cores (unchanged internals);
// bf16 output (feeds proj GEMM A).
// grid (T/64, B*H), 128 threads = 4 warps.
// ---------------------------------------------------------------------------
__global__ __launch_bounds__(128)
void attn_tc(const float* __restrict__ Q, const float* __restrict__ K,
             const float* __restrict__ V, __nv_bfloat16* __restrict__ O)
{
    __shared__ uint32_t KtPs[64][68];
    __shared__ uint32_t Vs[64][68];

    const int qt = blockIdx.x;
    const int b  = blockIdx.y >> 4;
    const int h  = blockIdx.y & 15;
    const int tid = threadIdx.x;
    const int w = tid >> 5, lane = tid & 31;
    const int r = lane >> 2, c = lane & 3;
    const size_t qrow0 = (size_t)b * TSEQ + qt * 64;

    // Stage Q (pre-scaled by 1/8, exact) into Vs, then build A-fragments
    for (int i = tid; i < 4096; i += 128) {
        const int rr = i >> 6, cc = i & 63;
        Vs[rr][cc] = __float_as_uint(Q[(qrow0 + rr) * CDIM + h * 64 + cc] * 0.125f);
    }
    __syncthreads();

    uint32_t qf[8][4];
    #pragma unroll
    for (int s = 0; s < 8; s++) {
        qf[s][0] = f2tf(__uint_as_float(Vs[16 * w + r    ][8 * s + c    ]));
        qf[s][1] = f2tf(__uint_as_float(Vs[16 * w + r + 8][8 * s + c    ]));
        qf[s][2] = f2tf(__uint_as_float(Vs[16 * w + r    ][8 * s + c + 4]));
        qf[s][3] = f2tf(__uint_as_float(Vs[16 * w + r + 8][8 * s + c + 4]));
    }

    float of[8][4];
    #pragma unroll
    for (int ni = 0; ni < 8; ni++)
        #pragma unroll
        for (int q = 0; q < 4; q++) of[ni][q] = 0.f;
    float m2[2] = {-1e30f, -1e30f};
    float l2[2] = {0.f, 0.f};

    for (int kt = 0; kt <= qt; kt++) {
        const size_t kr0 = (size_t)b * TSEQ + kt * 64;
        __syncthreads();

        for (int i = tid; i < 4096; i += 128) {
            const int rr = i >> 6, cc = i & 63;
            const size_t g = (kr0 + rr) * CDIM + h * 64 + cc;
            KtPs[cc][rr] = f2tf(K[g]);
            Vs[rr][cc]   = f2tf(V[g]);
        }
        __syncthreads();

        float sv[8][4];
        #pragma unroll
        for (int ni = 0; ni < 8; ni++)
            #pragma unroll
            for (int q = 0; q < 4; q++) sv[ni][q] = 0.f;

        #pragma unroll
        for (int s = 0; s < 8; s++) {
            uint32_t kb[8][2];
            #pragma unroll
            for (int ni = 0; ni < 8; ni++) {
                kb[ni][0] = KtPs[8 * s + c    ][8 * ni + r];
                kb[ni][1] = KtPs[8 * s + c + 4][8 * ni + r];
            }
            #pragma unroll
            for (int ni = 0; ni < 8; ni++) {
                asm volatile(
                    "mma.sync.aligned.m16n8k8.row.col.f32.tf32.tf32.f32 "
                    "{%0,%1,%2,%3}, {%4,%5,%6,%7}, {%8,%9}, {%0,%1,%2,%3};\n"
                    : "+f"(sv[ni][0]), "+f"(sv[ni][1]), "+f"(sv[ni][2]), "+f"(sv[ni][3])
                    : "r"(qf[s][0]), "r"(qf[s][1]), "r"(qf[s][2]), "r"(qf[s][3]),
                      "r"(kb[ni][0]), "r"(kb[ni][1]));
            }
        }

        if (kt == qt) {
            #pragma unroll
            for (int ni = 0; ni < 8; ni++)
                #pragma unroll
                for (int q = 0; q < 4; q++) {
                    const int col  = 8 * ni + 2 * c + (q & 1);
                    const int rowl = 16 * w + r + 8 * (q >> 1);
                    if (col > rowl) sv[ni][q] = -1e30f;
                }
        }

        float alpha[2];
        #pragma unroll
        for (int hh = 0; hh < 2; hh++) {
            float mt = -1e30f;
            #pragma unroll
            for (int ni = 0; ni < 8; ni++) {
                mt = fmaxf(mt, sv[ni][2 * hh]);
                mt = fmaxf(mt, sv[ni][2 * hh + 1]);
            }
            mt = fmaxf(mt, __shfl_xor_sync(0xffffffffu, mt, 1));
            mt = fmaxf(mt, __shfl_xor_sync(0xffffffffu, mt, 2));
            const float mnew = fmaxf(m2[hh], mt);
            alpha[hh] = __expf(m2[hh] - mnew);
            float ls = 0.f;
            #pragma unroll
            for (int ni = 0; ni < 8; ni++) {
                float p0 = __expf(sv[ni][2 * hh]     - mnew);
                float p1 = __expf(sv[ni][2 * hh + 1] - mnew);
                sv[ni][2 * hh] = p0; sv[ni][2 * hh + 1] = p1;
                ls += p0 + p1;
            }
            ls += __shfl_xor_sync(0xffffffffu, ls, 1);
            ls += __shfl_xor_sync(0xffffffffu, ls, 2);
            l2[hh] = l2[hh] * alpha[hh] + ls;
            m2[hh] = mnew;
        }
        #pragma unroll
        for (int ni = 0; ni < 8; ni++) {
            of[ni][0] *= alpha[0]; of[ni][1] *= alpha[0];
            of[ni][2] *= alpha[1]; of[ni][3] *= alpha[1];
        }

        __syncthreads();
        #pragma unroll
        for (int ni = 0; ni < 8; ni++) {
            const int col = 8 * ni + 2 * c;
            KtPs[16 * w + r    ][col]     = f2tf(sv[ni][0]);
            KtPs[16 * w + r    ][col + 1] = f2tf(sv[ni][1]);
            KtPs[16 * w + r + 8][col]     = f2tf(sv[ni][2]);
            KtPs[16 * w + r + 8][col + 1] = f2tf(sv[ni][3]);
        }
        __syncthreads();

        #pragma unroll
        for (int s = 0; s < 8; s++) {
            uint32_t pa[4];
            pa[0] = KtPs[16 * w + r    ][8 * s + c    ];
            pa[1] = KtPs[16 * w + r + 8][8 * s + c    ];
            pa[2] = KtPs[16 * w + r    ][8 * s + c + 4];
            pa[3] = KtPs[16 * w + r + 8][8 * s + c + 4];
            #pragma unroll
            for (int ni = 0; ni < 8; ni++) {
                uint32_t vb0 = Vs[8 * s + c    ][8 * ni + r];
                uint32_t vb1 = Vs[8 * s + c + 4][8 * ni + r];
                asm volatile(
                    "mma.sync.aligned.m16n8k8.row.col.f32.tf32.tf32.f32 "
                    "{%0,%1,%2,%3}, {%4,%5,%6,%7}, {%8,%9}, {%0,%1,%2,%3};\n"
                    : "+f"(of[ni][0]), "+f"(of[ni][1]), "+f"(of[ni][2]), "+f"(of[ni][3])
                    : "r"(pa[0]), "r"(pa[1]), "r"(pa[2]), "r"(pa[3]),
                      "r"(vb0), "r"(vb1));
            }
        }
    }

    const float inv0 = 1.0f / l2[0];
    const float inv1 = 1.0f / l2[1];
    #pragma unroll
    for (int ni = 0; ni < 8; ni++) {
        const size_t row = qrow0 + 16 * w + r;
        const int col = h * 64 + 8 * ni + 2 * c;
        ((uint32_t*)O)[(row * CDIM + col) >> 1] =
            packbf(of[ni][0] * inv0, of[ni][1] * inv0);
        ((uint32_t*)O)[((row + 8) * CDIM + col) >> 1] =
            packbf(of[ni][2] * inv1, of[ni][3] * inv1);
    }
}

// ---------------------------------------------------------------------------
// Launch
// ---------------------------------------------------------------------------
extern "C" void kernel_launch(void* const* d_in, const int* in_sizes, int n_in,
                              void* d_out, int out_size)
{
    const float* x   = (const float*)d_in[0];
    const float* Wq  = (const float*)d_in[1];
    const float* bq  = (const float*)d_in[2];
    const float* Wk  = (const float*)d_in[3];
    const float* bk  = (const float*)d_in[4];
    const float* Wv  = (const float*)d_in[5];
    const float* bv  = (const float*)d_in[6];
    const float* Wp  = (const float*)d_in[7];
    const float* bp  = (const float*)d_in[8];
    const float* W1  = (const float*)d_in[9];
    const float* b1  = (const float*)d_in[10];
    const float* W2  = (const float*)d_in[11];
    const float* b2  = (const float*)d_in[12];
    const float* g1  = (const float*)d_in[13];
    const float* be1 = (const float*)d_in[14];
    const float* g2  = (const float*)d_in[15];
    const float* be2 = (const float*)d_in[16];
    float* out = (float*)d_out;

    float *q, *k, *v, *x1;
    __nv_bfloat16 *lnb, *ab, *hb, *wq, *wk, *wv, *wp, *w1, *w2;
    cudaGetSymbolAddress((void**)&q,   g_q);
    cudaGetSymbolAddress((void**)&k,   g_k);
    cudaGetSymbolAddress((void**)&v,   g_v);
    cudaGetSymbolAddress((void**)&x1,  g_x1);
    cudaGetSymbolAddress((void**)&lnb, g_lnb);
    cudaGetSymbolAddress((void**)&ab,  g_ab);
    cudaGetSymbolAddress((void**)&hb,  g_hb);
    cudaGetSymbolAddress((void**)&wq,  g_wq);
    cudaGetSymbolAddress((void**)&wk,  g_wk);
    cudaGetSymbolAddress((void**)&wv,  g_wv);
    cudaGetSymbolAddress((void**)&wp,  g_wp);
    cudaGetSymbolAddress((void**)&w1,  g_w1);
    cudaGetSymbolAddress((void**)&w2,  g_w2);

    const dim3 blk(256);

    // Weights -> bf16 (one-time per replay, ~13us total)
    f2b_kernel<<<CDIM * CDIM / 2048, blk>>>(Wq, wq);
    f2b_kernel<<<CDIM * CDIM / 2048, blk>>>(Wk, wk);
    f2b_kernel<<<CDIM * CDIM / 2048, blk>>>(Wv, wv);
    f2b_kernel<<<CDIM * CDIM / 2048, blk>>>(Wp, wp);
    f2b_kernel<<<CDIM * FFDIM / 2048, blk>>>(W1, w1);
    f2b_kernel<<<FFDIM * CDIM / 2048, blk>>>(W2, w2);

    ln_kernel<<<MTOK, blk>>>(x, g1, be1, lnb);

    QKVParams qkv = {wq, wk, wv, bq, bk, bv, q, k, v};
    gemm_bf_qkv<<<dim3(CDIM / 128, MTOK / 128, 3), blk>>>(lnb, qkv);

    attn_tc<<<dim3(TSEQ / 64, BSZ * NHEAD), 128>>>(q, k, v, ab);

    gemm_bf<1, 0><<<dim3(CDIM / 128, MTOK / 128), blk>>>(ab, wp, bp, x, x1, CDIM, CDIM);

    ln_kernel<<<MTOK, blk>>>(x1, g2, be2, lnb);

    gemm_bf<2, 1><<<dim3(FFDIM / 128, MTOK / 128), blk>>>(lnb, w1, b1, nullptr, hb, FFDIM, CDIM);
    gemm_bf<1, 0><<<dim3(CDIM / 128, MTOK / 128), blk>>>(hb, w2, b2, x1, out, CDIM, FFDIM);
}